// round 3
// baseline (speedup 1.0000x reference)
#include <cuda_runtime.h>
#include <cstdint>

#define H       64
#define INP     32
#define NF      96
#define TT      128
#define BM      56      // batch elements per CTA
#define BMP     60      // padded row width (floats)
#define NTHR    448     // 64 units * 7 groups
#define BPT     8       // batch elements per thread (4 packed pairs)

typedef unsigned long long ull;

// shared memory layout (floats)
#define OFF_W4    0                         // [96][64] float4 : {wi,wf,wg,wo}; rows 0..31 = W_ih, 32..95 = W_hh
#define OFF_B4    (OFF_W4 + NF*H*4)         // [64] float4
#define OFF_XS    (OFF_B4 + H*4)            // [2][32][BMP]
#define OFF_HS    (OFF_XS + 2*INP*BMP)      // [2][64][BMP]
#define SMEM_FLOATS (OFF_HS + 2*H*BMP)
#define SMEM_BYTES  (SMEM_FLOATS * 4)

__device__ __forceinline__ ull bcast2(float w) {
    ull r; asm("mov.b64 %0, {%1, %1};" : "=l"(r) : "f"(w)); return r;
}
__device__ __forceinline__ void unpack2(ull v, float& lo, float& hi) {
    asm("mov.b64 {%0, %1}, %2;" : "=f"(lo), "=f"(hi) : "l"(v));
}
__device__ __forceinline__ void fma2(ull& d, ull a, ull b) {
    asm("fma.rn.f32x2 %0, %1, %2, %0;" : "+l"(d) : "l"(a), "l"(b));
}

__device__ __forceinline__ float fsig(float v) {
    return __fdividef(1.0f, 1.0f + __expf(-v));
}
__device__ __forceinline__ float ftanh(float v) {
    float a = fabsf(v);
    float e = __expf(-2.0f * a);
    float r = __fdividef(1.0f - e, 1.0f + e);
    return copysignf(r, v);
}

// accumulate N features: wbase = w4 + row0*256 + k*4 ; sbase = state + b0
template<int N>
__device__ __forceinline__ void accum(const float* __restrict__ wbase,
                                      const float* __restrict__ sbase,
                                      ull a0[4], ull a1[4], ull a2[4], ull a3[4])
{
#pragma unroll 4
    for (int j = 0; j < N; ++j) {
        float4 w = *(const float4*)(wbase + j * 256);
        ull wi = bcast2(w.x), wf = bcast2(w.y),
            wg = bcast2(w.z), wo = bcast2(w.w);
        ulonglong2 va = *(const ulonglong2*)(sbase + j * BMP);
        ulonglong2 vb = *(const ulonglong2*)(sbase + j * BMP + 4);
        ull pr[4] = {va.x, va.y, vb.x, vb.y};
#pragma unroll
        for (int q = 0; q < 4; ++q) {
            fma2(a0[q], wi, pr[q]);
            fma2(a1[q], wf, pr[q]);
            fma2(a2[q], wg, pr[q]);
            fma2(a3[q], wo, pr[q]);
        }
    }
}

__global__ void __launch_bounds__(NTHR, 1)
lstm_kernel(const float* __restrict__ x,
            const float* __restrict__ W_ih,
            const float* __restrict__ W_hh,
            const float* __restrict__ b_ih,
            const float* __restrict__ b_hh,
            const float* __restrict__ W_fc,
            const float* __restrict__ b_fc,
            float* __restrict__ out,
            int Btotal)
{
    extern __shared__ float sm[];
    float* w4 = sm + OFF_W4;
    float* b4 = sm + OFF_B4;
    float* xs = sm + OFF_XS;   // xs[buf*INP*BMP + j*BMP + b]
    float* hs = sm + OFF_HS;   // hs[buf*H*BMP   + j*BMP + b]

    const int tid   = threadIdx.x;
    const int bbase = blockIdx.x * BM;
    const int k     = tid & 63;
    const int grp   = tid >> 6;
    const int b0    = grp * BPT;

    // ---- stage weights into packed-gate layout (one-time) ----
    for (int n = tid; n < NF * 256; n += NTHR) {
        int j = n >> 8, g = n & 255;
        float v = (j < INP) ? W_ih[g * INP + j] : W_hh[g * H + (j - INP)];
        int kk = g & 63, gate = g >> 6;
        w4[(j * H + kk) * 4 + gate] = v;
    }
    for (int n = tid; n < 256; n += NTHR) {
        int kk = n & 63, gate = n >> 6;
        b4[kk * 4 + gate] = b_ih[gate * H + kk] + b_hh[gate * H + kk];
    }
    for (int n = tid; n < 2 * H * BMP; n += NTHR)
        hs[n] = 0.0f;

    // ---- x staging: each thread owns one float4 per step ----
    const int lb = tid >> 3;                 // 0..55 batch within tile
    const int iv = (tid & 7) * 4;            // input feature base
    const bool bvalid = (bbase + lb) < Btotal;
    // clamped (branch-free) source pointer: invalid batches read batch 0 (discarded)
    const float* xrowS = x + (bvalid ? ((size_t)(bbase + lb) * TT * INP) : 0) + iv;

    // stage x(0) -> xb0, x(1) -> xb1, prefetch x(2)
    {
        float4 x0 = *(const float4*)(xrowS);
        float4 x1 = *(const float4*)(xrowS + INP);
        float* xb0 = xs;
        float* xb1 = xs + INP * BMP;
        xb0[(iv + 0) * BMP + lb] = x0.x;  xb0[(iv + 1) * BMP + lb] = x0.y;
        xb0[(iv + 2) * BMP + lb] = x0.z;  xb0[(iv + 3) * BMP + lb] = x0.w;
        xb1[(iv + 0) * BMP + lb] = x1.x;  xb1[(iv + 1) * BMP + lb] = x1.y;
        xb1[(iv + 2) * BMP + lb] = x1.z;  xb1[(iv + 3) * BMP + lb] = x1.w;
    }
    float4 xr = *(const float4*)(xrowS + 2 * INP);   // x(2)
    __syncthreads();

    float c[BPT];
#pragma unroll
    for (int b = 0; b < BPT; ++b) c[b] = 0.0f;

    const float4 bk = *(const float4*)&b4[k * 4];
    const ull bb0 = bcast2(bk.x), bb1 = bcast2(bk.y),
              bb2 = bcast2(bk.z), bb3 = bcast2(bk.w);

    const float* w4k  = w4 + k * 4;            // feature rows (x part, rows 0..31)
    const float* w4kh = w4 + 32 * 256 + k * 4; // h part (rows 32..95)

    // acc set A: gates for even step (already bias + Wx.x(t)); set B: odd step
    ull A0[4], A1[4], A2[4], A3[4], B0[4], B1[4], B2[4], B3[4];
#pragma unroll
    for (int q = 0; q < 4; ++q) { A0[q]=bb0; A1[q]=bb1; A2[q]=bb2; A3[q]=bb3; }
    accum<INP>(w4k, xs + b0, A0, A1, A2, A3);   // + Wx . x(0)

#define ACTIVATE(a0,a1,a2,a3,HN)                                          \
    {                                                                     \
        float* hn = (HN);                                                 \
        _Pragma("unroll")                                                 \
        for (int q = 0; q < 4; ++q) {                                     \
            float i0,i1,f0,f1,g0,g1,o0,o1;                                \
            unpack2(a0[q], i0, i1); unpack2(a1[q], f0, f1);               \
            unpack2(a2[q], g0, g1); unpack2(a3[q], o0, o1);               \
            float ig=fsig(i0), fg=fsig(f0), gg=ftanh(g0), og=fsig(o0);    \
            float cn = fmaf(fg, c[2*q], ig*gg);                           \
            c[2*q] = cn;                                                  \
            float hv0 = og * ftanh(cn);                                   \
            ig=fsig(i1); fg=fsig(f1); gg=ftanh(g1); og=fsig(o1);          \
            cn = fmaf(fg, c[2*q+1], ig*gg);                               \
            c[2*q+1] = cn;                                                \
            float hv1 = og * ftanh(cn);                                   \
            *(float2*)&hn[2*q] = make_float2(hv0, hv1);                   \
        }                                                                 \
    }

#define STAGE_X(XBW, T)                                                   \
    {                                                                     \
        float* xw = (XBW);                                                \
        xw[(iv+0)*BMP+lb]=xr.x; xw[(iv+1)*BMP+lb]=xr.y;                   \
        xw[(iv+2)*BMP+lb]=xr.z; xw[(iv+3)*BMP+lb]=xr.w;                   \
        int tn = (T) + 3; if (tn > TT-1) tn = TT-1;                       \
        xr = *(const float4*)(xrowS + (size_t)tn * INP);                  \
    }

    float* const hb0 = hs;
    float* const hb1 = hs + H * BMP;
    float* const xb0 = xs;
    float* const xb1 = xs + INP * BMP;

    for (int t = 0; t < TT; t += 2) {
        // ---- substep even t: h(t-1) in hb0 -> h(t) to hb1; x(t+1) in xb1 ----
        accum<H>(w4kh, hb0 + b0, A0, A1, A2, A3);          // + Wh . h(t-1)
#pragma unroll
        for (int q = 0; q < 4; ++q) { B0[q]=bb0; B1[q]=bb1; B2[q]=bb2; B3[q]=bb3; }
        accum<INP>(w4k, xb1 + b0, B0, B1, B2, B3);         // next-step x-part (independent)
        ACTIVATE(A0, A1, A2, A3, hb1 + k * BMP + b0);      // MUFU overlaps accum above
        STAGE_X(xb0, t);                                   // x(t+2) -> xb0, prefetch x(t+3)
        __syncthreads();

        // ---- substep odd t+1: h(t) in hb1 -> h(t+1) to hb0; x(t+2) in xb0 ----
        accum<H>(w4kh, hb1 + b0, B0, B1, B2, B3);
#pragma unroll
        for (int q = 0; q < 4; ++q) { A0[q]=bb0; A1[q]=bb1; A2[q]=bb2; A3[q]=bb3; }
        accum<INP>(w4k, xb0 + b0, A0, A1, A2, A3);
        ACTIVATE(B0, B1, B2, B3, hb0 + k * BMP + b0);
        STAGE_X(xb1, t + 1);
        __syncthreads();
    }

    // ---- final FC: h(127) lives in hb0 ----
    const int ob = tid >> 3;
    const int oo = tid & 7;
    if (ob < BM && (bbase + ob) < Btotal) {
        float a = b_fc[oo];
#pragma unroll 8
        for (int kk = 0; kk < H; ++kk)
            a = fmaf(hb0[kk * BMP + ob], W_fc[oo * H + kk], a);
        out[(size_t)(bbase + ob) * 8 + oo] = a;
    }
}

extern "C" void kernel_launch(void* const* d_in, const int* in_sizes, int n_in,
                              void* d_out, int out_size) {
    const float* x    = (const float*)d_in[0];
    const float* W_ih = (const float*)d_in[1];
    const float* W_hh = (const float*)d_in[2];
    const float* b_ih = (const float*)d_in[3];
    const float* b_hh = (const float*)d_in[4];
    const float* W_fc = (const float*)d_in[5];
    const float* b_fc = (const float*)d_in[6];
    float* out = (float*)d_out;

    const int B = in_sizes[0] / (TT * INP);   // 8192
    const int grid = (B + BM - 1) / BM;       // 147

    cudaFuncSetAttribute(lstm_kernel,
                         cudaFuncAttributeMaxDynamicSharedMemorySize,
                         SMEM_BYTES);
    lstm_kernel<<<grid, NTHR, SMEM_BYTES>>>(x, W_ih, W_hh, b_ih, b_hh,
                                            W_fc, b_fc, out, B);
}